// round 1
// baseline (speedup 1.0000x reference)
#include <cuda_runtime.h>
#include <cuda_bf16.h>
#include <cstdint>

// ---------------------------------------------------------------------------
// YOLOv3 post-process: decode + top-k + class-shifted greedy NMS
// B=32 images, C=255 channels, G=64 grid, 3 anchors, 80 classes
// ---------------------------------------------------------------------------

#define BATCH 32
#define GRID 64
#define GG   4096          // 64*64
#define NBOX 12288         // GG*3
#define NCLS 80
#define TOPK 1024
#define MONO_NEGINF 0x007FFFFFu   // mono encoding of -inf float

// -------------------- device scratch (no allocations allowed) --------------
__device__ float              g_det[(size_t)BATCH * NBOX * 8];     // x1,y1,x2,y2,conf,maxval,clsidx,pad
__device__ unsigned long long g_key[(size_t)BATCH * NBOX];
__device__ float              g_cand[(size_t)BATCH * TOPK * 8];    // sx1,sy1,sx2,sy2,area,cls,valid,pad
__device__ int                g_topidx[BATCH * TOPK];
__device__ unsigned           g_mask[(size_t)BATCH * TOPK * 32];   // suppression bitmask rows
__device__ unsigned           g_rownz[BATCH * 32];                 // per-image 1024-bit "row nonzero" set

// -------------------- K1: decode -------------------------------------------
// thread <-> spatial index s (memory-linear within a channel) for coalescing.
__global__ void k_decode(const float* __restrict__ in)
{
    int b = blockIdx.y;
    int s = blockIdx.x * blockDim.x + threadIdx.x;   // 0..4095
    const float* base = in + (size_t)b * 255 * GG + s;

    int g1 = s >> 6;
    int g2 = s & 63;
    int p  = (g2 << 6) | g1;                         // row-major (g2,g1) index used by reference

    #pragma unroll
    for (int a = 0; a < 3; a++) {
        const float* cb = base + (size_t)a * 85 * GG;
        float t0 = cb[0 * GG];
        float t1 = cb[1 * GG];
        float t2 = cb[2 * GG];
        float t3 = cb[3 * GG];
        float t4 = cb[4 * GG];

        // argmax over 80 class scores, first-max wins (matches jnp.argmax)
        float best = cb[5 * GG];
        int   bi   = 0;
        #pragma unroll 8
        for (int d = 1; d < NCLS; d++) {
            float v = cb[(5 + d) * GG];
            if (v > best) { best = v; bi = d; }
        }

        int n = 3 * p + a;
        float xo = (float)((n >> 6) & 63);
        float yo = (float)(n & 63);

        float cx = __fadd_rn(t0, xo);
        float cy = __fadd_rn(t1, yo);
        float hw = __fmul_rn(t2, 0.5f);
        float hh = __fmul_rn(t3, 0.5f);
        float x1 = __fsub_rn(cx, hw);
        float y1 = __fsub_rn(cy, hh);
        float x2 = __fadd_rn(cx, hw);
        float y2 = __fadd_rn(cy, hh);

        float conf = 1.0f / (1.0f + expf(-t4));

        float* dr = &g_det[(((size_t)b * NBOX) + n) * 8];
        dr[0] = x1; dr[1] = y1; dr[2] = x2; dr[3] = y2;
        dr[4] = conf; dr[5] = best; dr[6] = (float)bi;

        // ranking key: monotone-encoded logit (exact order == conf order),
        // logit<=0 -> shared -inf bucket (stable by index, like jax top_k).
        unsigned mono;
        if (t4 > 0.0f) mono = __float_as_uint(t4) ^ 0x80000000u;
        else           mono = MONO_NEGINF;
        g_key[(size_t)b * NBOX + n] =
            ((unsigned long long)mono << 32) | (unsigned)(~(unsigned)n);
    }
}

// -------------------- K2: exact top-1024 select + sort ----------------------
// One block per image. MSB radix select (8x 8-bit digits) finds the exact
// 1024th-largest 64-bit key (keys are distinct), then compact + bitonic sort.
__global__ void k_select()
{
    int b   = blockIdx.x;
    int tid = threadIdx.x;   // 1024 threads

    __shared__ unsigned            hist[256];
    __shared__ unsigned long long  sh_prefix;
    __shared__ unsigned            sh_needed;
    __shared__ unsigned long long  s_sel[TOPK];
    __shared__ unsigned            s_cnt;

    const unsigned long long* keys = g_key + (size_t)b * NBOX;

    if (tid == 0) { sh_prefix = 0ull; sh_needed = TOPK; s_cnt = 0; }
    __syncthreads();

    for (int pass = 0; pass < 8; pass++) {
        if (tid < 256) hist[tid] = 0;
        __syncthreads();
        unsigned long long pref = sh_prefix;
        int shift = 56 - 8 * pass;
        for (int e = tid; e < NBOX; e += 1024) {
            unsigned long long k = keys[e];
            bool match = (pass == 0) || (((k ^ pref) >> (shift + 8)) == 0);
            if (match) atomicAdd(&hist[(unsigned)(k >> shift) & 255u], 1u);
        }
        __syncthreads();
        if (tid == 0) {
            unsigned needed = sh_needed;
            unsigned acc = 0;
            int d = 255;
            for (; d >= 0; d--) {
                unsigned c = hist[d];
                if (acc + c >= needed) break;
                acc += c;
            }
            if (d < 0) d = 0;  // defensive; cannot happen
            sh_prefix = pref | ((unsigned long long)(unsigned)d << shift);
            sh_needed = needed - acc;
        }
        __syncthreads();
    }

    unsigned long long pivot = sh_prefix;   // exact 1024th-largest key
    for (int e = tid; e < NBOX; e += 1024) {
        unsigned long long k = keys[e];
        if (k >= pivot) {
            unsigned pos = atomicAdd(&s_cnt, 1u);
            if (pos < TOPK) s_sel[pos] = k;
        }
    }
    __syncthreads();

    // bitonic sort descending (1024 elements, 1024 threads)
    for (unsigned k = 2; k <= TOPK; k <<= 1) {
        for (unsigned j = k >> 1; j > 0; j >>= 1) {
            unsigned i = tid;
            unsigned ixj = i ^ j;
            if (ixj > i) {
                unsigned long long va = s_sel[i];
                unsigned long long vb = s_sel[ixj];
                bool descBlock = ((i & k) == 0);
                if (descBlock ? (va < vb) : (va > vb)) {
                    s_sel[i]   = vb;
                    s_sel[ixj] = va;
                }
            }
            __syncthreads();
        }
    }

    // emit candidate row at rank=tid
    unsigned long long kk = s_sel[tid];
    unsigned idx  = ~(unsigned)kk;            // recover box index
    unsigned mono = (unsigned)(kk >> 32);
    int valid = (mono > 0x80000000u) ? 1 : 0; // conf > 0.5  <=>  logit > 0

    const float* dr = &g_det[((size_t)b * NBOX + idx) * 8];
    float cls = dr[6];
    float off = __fmul_rn(cls, 10000.0f);
    float sx1 = __fadd_rn(dr[0], off);
    float sy1 = __fadd_rn(dr[1], off);
    float sx2 = __fadd_rn(dr[2], off);
    float sy2 = __fadd_rn(dr[3], off);
    float area = __fmul_rn(__fsub_rn(sx2, sx1), __fsub_rn(sy2, sy1));

    float* cr = &g_cand[((size_t)b * TOPK + tid) * 8];
    cr[0] = sx1; cr[1] = sy1; cr[2] = sx2; cr[3] = sy2;
    cr[4] = area; cr[5] = cls; cr[6] = valid ? 1.0f : 0.0f; cr[7] = 0.0f;
    g_topidx[b * TOPK + tid] = (int)idx;
}

// -------------------- K3: pairwise suppression bitmask ----------------------
// grid (32 row-tiles, 32 images), 1024 threads = 32 warps.
// warp r handles row i = rt*32+r; lane w owns mask word w (cols 32w..32w+31).
__global__ void k_mask()
{
    int rt  = blockIdx.x;
    int b   = blockIdx.y;
    int tid = threadIdx.x;
    int warp = tid >> 5;
    int lane = tid & 31;

    __shared__ float sx1[TOPK], sy1[TOPK], sx2[TOPK], sy2[TOPK], sar[TOPK], scl[TOPK];
    __shared__ unsigned s_any[32];

    for (int e = tid; e < TOPK; e += 1024) {
        const float* cr = &g_cand[((size_t)b * TOPK + e) * 8];
        sx1[e] = cr[0]; sy1[e] = cr[1]; sx2[e] = cr[2];
        sy2[e] = cr[3]; sar[e] = cr[4]; scl[e] = cr[5];
    }
    __syncthreads();

    int i = rt * 32 + warp;
    float ax1 = sx1[i], ay1 = sy1[i], ax2 = sx2[i], ay2 = sy2[i];
    float aa = sar[i], ac = scl[i];

    unsigned word = 0;
    int j0 = lane * 32;
    #pragma unroll 4
    for (int jj = 0; jj < 32; jj++) {
        int j = j0 + jj;
        if (j > i && scl[j] == ac) {   // class offset 10000 => cross-class IoU can never pass
            float lx = fmaxf(ax1, sx1[j]);
            float ly = fmaxf(ay1, sy1[j]);
            float rx = fminf(ax2, sx2[j]);
            float ry = fminf(ay2, sy2[j]);
            float w  = fmaxf(__fsub_rn(rx, lx), 0.0f);
            float h  = fmaxf(__fsub_rn(ry, ly), 0.0f);
            float inter = __fmul_rn(w, h);
            float denom = __fadd_rn(__fsub_rn(__fadd_rn(aa, sar[j]), inter), 1e-9f);
            float iou   = __fdiv_rn(inter, denom);
            if (iou > 0.4f) word |= (1u << jj);
        }
    }
    g_mask[(((size_t)b * TOPK) + i) * 32 + lane] = word;

    unsigned nzb = __ballot_sync(0xffffffffu, word != 0u);
    if (lane == 0) s_any[warp] = (nzb != 0u) ? 1u : 0u;
    __syncthreads();
    if (tid < 32) {
        unsigned bits = __ballot_sync(0xffffffffu, s_any[tid] != 0u);
        if (tid == 0) g_rownz[b * 32 + rt] = bits;
    }
}

// -------------------- K4: sequential resolve (sparse) + output --------------
// Since mask[i] only sets bits j>i, only rows with nonzero masks can change
// state; everything else is read-only. One warp resolves the scan.
__global__ void k_scan(float* __restrict__ out, int out_size)
{
    int b   = blockIdx.x;
    int tid = threadIdx.x;   // 1024 threads

    __shared__ unsigned removed[32];
    if (tid < 32) removed[tid] = 0;
    __syncthreads();

    if (tid < 32) {
        unsigned lane = tid;
        for (int rt = 0; rt < 32; rt++) {
            unsigned nz = g_rownz[b * 32 + rt];   // uniform across lanes
            while (nz) {
                int r = __ffs(nz) - 1;
                nz &= nz - 1;
                int i = rt * 32 + r;
                int kept = 0;
                if (lane == 0) {
                    unsigned bit = (removed[i >> 5] >> (i & 31)) & 1u;
                    float v = g_cand[((size_t)b * TOPK + i) * 8 + 6];
                    kept = (!bit) && (v != 0.0f);
                }
                kept = __shfl_sync(0xffffffffu, kept, 0);
                if (kept)
                    removed[lane] |= g_mask[(((size_t)b * TOPK) + i) * 32 + lane];
                __syncwarp(0xffffffffu);
            }
        }
    }
    __syncthreads();

    // emit
    int j = tid;
    unsigned bit = (removed[j >> 5] >> (j & 31)) & 1u;
    const float* cr = &g_cand[((size_t)b * TOPK + j) * 8];
    bool keep = (cr[6] != 0.0f) && !bit;
    int idx = g_topidx[b * TOPK + j];
    const float* dr = &g_det[((size_t)b * NBOX + idx) * 8];

    size_t base = ((size_t)b * TOPK + j) * 7;
    #pragma unroll
    for (int k = 0; k < 7; k++)
        out[base + k] = keep ? __fmul_rn(8.0f, dr[k]) : 0.0f;

    if (out_size >= BATCH * TOPK * 7 + BATCH * TOPK)
        out[(size_t)BATCH * TOPK * 7 + (size_t)b * TOPK + j] = keep ? 1.0f : 0.0f;
}

// -------------------- launch -----------------------------------------------
extern "C" void kernel_launch(void* const* d_in, const int* in_sizes, int n_in,
                              void* d_out, int out_size)
{
    const float* in = (const float*)d_in[0];
    float* out = (float*)d_out;

    k_decode<<<dim3(16, BATCH), 256>>>(in);
    k_select<<<BATCH, 1024>>>();
    k_mask<<<dim3(32, BATCH), 1024>>>();
    k_scan<<<BATCH, 1024>>>(out, out_size);
}

// round 2
// speedup vs baseline: 1.8091x; 1.8091x over previous
#include <cuda_runtime.h>
#include <cuda_bf16.h>
#include <cstdint>

// ---------------------------------------------------------------------------
// YOLOv3 post-process: decode + top-k + class-shifted greedy NMS
// B=32 images, C=255 channels, G=64 grid, 3 anchors, 80 classes
// ---------------------------------------------------------------------------

#define BATCH 32
#define GRID 64
#define GG   4096          // 64*64
#define NBOX 12288         // GG*3
#define NCLS 80
#define TOPK 1024
#define MONO_NEGINF 0x007FFFFFu   // mono encoding of -inf float

// -------------------- device scratch (no allocations allowed) --------------
// g_det rows stored at STORAGE index m = a*GG + s (coalesced writes).
__device__ float              g_det[(size_t)BATCH * NBOX * 8];     // x1,y1,x2,y2,conf,maxval,clsidx,pad
__device__ unsigned long long g_key[(size_t)BATCH * NBOX];         // mono(logit)<<32 | ~n (logical n)
__device__ float              g_cand[(size_t)BATCH * TOPK * 8];    // sx1,sy1,sx2,sy2,area,cls,valid,pad
__device__ int                g_topidx[BATCH * TOPK];              // storage index m of ranked box
__device__ unsigned           g_mask[(size_t)BATCH * TOPK * 32];   // suppression bitmask rows
__device__ unsigned           g_rownz[BATCH * 32];                 // per-image 1024-bit "row has nonzero mask"
__device__ unsigned           g_removed[BATCH * 32];               // resolved removed bitset

// -------------------- K1: decode -------------------------------------------
// thread <-> spatial index s (memory-linear within a channel): coalesced reads
// AND coalesced writes (det row stored at m = a*GG + s).
__global__ void k_decode(const float* __restrict__ in)
{
    int b = blockIdx.y;
    int s = blockIdx.x * blockDim.x + threadIdx.x;   // 0..4095
    const float* base = in + (size_t)b * 255 * GG + s;

    int p = ((s & 63) << 6) | (s >> 6);              // logical grid index (g2<<6)|g1

    #pragma unroll
    for (int a = 0; a < 3; a++) {
        const float* cb = base + (size_t)a * 85 * GG;
        float t0 = cb[0 * GG];
        float t1 = cb[1 * GG];
        float t2 = cb[2 * GG];
        float t3 = cb[3 * GG];
        float t4 = cb[4 * GG];

        // argmax over 80 class scores, first-max wins (matches jnp.argmax)
        float best = cb[5 * GG];
        int   bi   = 0;
        #pragma unroll 8
        for (int d = 1; d < NCLS; d++) {
            float v = cb[(5 + d) * GG];
            if (v > best) { best = v; bi = d; }
        }

        int n = 3 * p + a;                           // logical row index
        float xo = (float)((n >> 6) & 63);
        float yo = (float)(n & 63);

        float cx = __fadd_rn(t0, xo);
        float cy = __fadd_rn(t1, yo);
        float hw = __fmul_rn(t2, 0.5f);
        float hh = __fmul_rn(t3, 0.5f);
        float x1 = __fsub_rn(cx, hw);
        float y1 = __fsub_rn(cy, hh);
        float x2 = __fadd_rn(cx, hw);
        float y2 = __fadd_rn(cy, hh);

        float conf = 1.0f / (1.0f + expf(-t4));

        int m = a * GG + s;                          // storage index (coalesced)
        float4* dr = reinterpret_cast<float4*>(&g_det[(((size_t)b * NBOX) + m) * 8]);
        dr[0] = make_float4(x1, y1, x2, y2);
        dr[1] = make_float4(conf, best, (float)bi, 0.0f);

        // ranking key: monotone-encoded logit (exact order == conf order),
        // logit<=0 -> shared -inf bucket (stable by index, like jax top_k).
        unsigned mono;
        if (t4 > 0.0f) mono = __float_as_uint(t4) ^ 0x80000000u;
        else           mono = MONO_NEGINF;
        g_key[(size_t)b * NBOX + m] =
            ((unsigned long long)mono << 32) | (unsigned)(~(unsigned)n);
    }
}

// -------------------- K2: exact top-1024 select + sort ----------------------
// One block per image. MSB radix select (8x 8-bit digits) finds the exact
// 1024th-largest 64-bit key (keys are distinct). The 256-bin threshold search
// is done by warp 0 with a shfl suffix-scan (8 bins/lane) — no serial loop.
__global__ void k_select()
{
    int b   = blockIdx.x;
    int tid = threadIdx.x;   // 1024 threads

    __shared__ unsigned            hist[256];
    __shared__ unsigned long long  sh_prefix;
    __shared__ unsigned            sh_needed;
    __shared__ unsigned long long  s_sel[TOPK];
    __shared__ unsigned            s_cnt;

    const unsigned long long* keys = g_key + (size_t)b * NBOX;

    if (tid == 0) { sh_prefix = 0ull; sh_needed = TOPK; s_cnt = 0; }
    __syncthreads();

    for (int pass = 0; pass < 8; pass++) {
        unsigned long long pref   = sh_prefix;   // state loads (ordered vs writes
        unsigned           needed = sh_needed;   //  by the syncthreads below)
        if (tid < 256) hist[tid] = 0;
        __syncthreads();

        int shift = 56 - 8 * pass;
        for (int e = tid; e < NBOX; e += 1024) {
            unsigned long long k = keys[e];
            bool match = (pass == 0) || (((k ^ pref) >> (shift + 8)) == 0);
            if (match) atomicAdd(&hist[(unsigned)(k >> shift) & 255u], 1u);
        }
        __syncthreads();

        if (tid < 32) {
            int lane = tid;
            int bbase = 255 - 8 * lane;          // lane owns bins bbase..bbase-7 (descending)
            unsigned c[8]; unsigned tot = 0;
            #pragma unroll
            for (int q = 0; q < 8; q++) { c[q] = hist[bbase - q]; tot += c[q]; }
            unsigned inc = tot;
            #pragma unroll
            for (int off = 1; off < 32; off <<= 1) {
                unsigned v = __shfl_up_sync(0xffffffffu, inc, off);
                if (lane >= off) inc += v;
            }
            unsigned excl = inc - tot;           // count in bins strictly above my batch
            if (excl < needed && needed <= inc) {   // threshold bin is in my batch
                unsigned run = excl; int d = bbase;
                #pragma unroll
                for (int q = 0; q < 8; q++) {
                    if (run + c[q] >= needed) { d = bbase - q; break; }
                    run += c[q];
                }
                sh_prefix = pref | ((unsigned long long)(unsigned)d << shift);
                sh_needed = needed - run;        // run = count strictly above bin d
            }
        }
        __syncthreads();
    }

    unsigned long long pivot = sh_prefix;   // exact 1024th-largest key
    for (int e = tid; e < NBOX; e += 1024) {
        unsigned long long k = keys[e];
        if (k >= pivot) {
            unsigned pos = atomicAdd(&s_cnt, 1u);
            if (pos < TOPK) s_sel[pos] = k;
        }
    }
    __syncthreads();

    // bitonic sort descending (1024 elements, 1024 threads)
    for (unsigned k = 2; k <= TOPK; k <<= 1) {
        for (unsigned j = k >> 1; j > 0; j >>= 1) {
            unsigned i = tid;
            unsigned ixj = i ^ j;
            if (ixj > i) {
                unsigned long long va = s_sel[i];
                unsigned long long vb = s_sel[ixj];
                bool descBlock = ((i & k) == 0);
                if (descBlock ? (va < vb) : (va > vb)) {
                    s_sel[i]   = vb;
                    s_sel[ixj] = va;
                }
            }
            __syncthreads();
        }
    }

    // emit candidate row at rank=tid
    unsigned long long kk = s_sel[tid];
    unsigned n    = ~(unsigned)kk;            // logical box index
    unsigned mono = (unsigned)(kk >> 32);
    int valid = (mono > 0x80000000u) ? 1 : 0; // conf > 0.5  <=>  logit > 0

    // logical n -> storage m
    int a = (int)(n % 3u);
    int p = (int)(n / 3u);
    int s = ((p & 63) << 6) | (p >> 6);
    int m = a * GG + s;

    const float4* dr = reinterpret_cast<const float4*>(&g_det[((size_t)b * NBOX + m) * 8]);
    float4 d0 = dr[0], d1 = dr[1];
    float cls = d1.z;
    float off = __fmul_rn(cls, 10000.0f);
    float sx1 = __fadd_rn(d0.x, off);
    float sy1 = __fadd_rn(d0.y, off);
    float sx2 = __fadd_rn(d0.z, off);
    float sy2 = __fadd_rn(d0.w, off);
    float area = __fmul_rn(__fsub_rn(sx2, sx1), __fsub_rn(sy2, sy1));

    float4* cr = reinterpret_cast<float4*>(&g_cand[((size_t)b * TOPK + tid) * 8]);
    cr[0] = make_float4(sx1, sy1, sx2, sy2);
    cr[1] = make_float4(area, cls, valid ? 1.0f : 0.0f, 0.0f);
    g_topidx[b * TOPK + tid] = m;
}

// -------------------- K3: pairwise suppression bitmask ----------------------
// grid (32 row-tiles, 32 images), 1024 threads = 32 warps.
// Warp r handles row i = rt*32+r. Lane owns column j = w*32+lane each step:
// consecutive-j shared loads (conflict-free) + __ballot_sync builds the word.
__global__ void k_mask()
{
    int rt  = blockIdx.x;
    int b   = blockIdx.y;
    int tid = threadIdx.x;
    int warp = tid >> 5;
    int lane = tid & 31;

    __shared__ float sx1[TOPK], sy1[TOPK], sx2[TOPK], sy2[TOPK], sar[TOPK], scl[TOPK];
    __shared__ unsigned s_any[32];

    for (int e = tid; e < TOPK; e += 1024) {
        const float4* cr = reinterpret_cast<const float4*>(&g_cand[((size_t)b * TOPK + e) * 8]);
        float4 c0 = cr[0], c1 = cr[1];
        sx1[e] = c0.x; sy1[e] = c0.y; sx2[e] = c0.z;
        sy2[e] = c0.w; sar[e] = c1.x; scl[e] = c1.y;
    }
    __syncthreads();

    int i = rt * 32 + warp;
    float ax1 = sx1[i], ay1 = sy1[i], ax2 = sx2[i], ay2 = sy2[i];
    float aa = sar[i], ac = scl[i];

    unsigned myword = 0;
    #pragma unroll 4
    for (int w = 0; w < 32; w++) {
        int j = (w << 5) + lane;
        bool sup = false;
        if (j > i && scl[j] == ac) {   // class offset 10000 => cross-class IoU can never pass
            float lx = fmaxf(ax1, sx1[j]);
            float ly = fmaxf(ay1, sy1[j]);
            float rx = fminf(ax2, sx2[j]);
            float ry = fminf(ay2, sy2[j]);
            float ww = fmaxf(__fsub_rn(rx, lx), 0.0f);
            float hh = fmaxf(__fsub_rn(ry, ly), 0.0f);
            float inter = __fmul_rn(ww, hh);
            float denom = __fadd_rn(__fsub_rn(__fadd_rn(aa, sar[j]), inter), 1e-9f);
            float iou   = __fdiv_rn(inter, denom);
            sup = iou > 0.4f;
        }
        unsigned word = __ballot_sync(0xffffffffu, sup);
        if (w == lane) myword = word;
    }
    g_mask[(((size_t)b * TOPK) + i) * 32 + lane] = myword;

    unsigned nzb = __ballot_sync(0xffffffffu, myword != 0u);
    if (lane == 0) s_any[warp] = nzb;
    __syncthreads();
    if (warp == 0) {
        unsigned bits = __ballot_sync(0xffffffffu, s_any[lane] != 0u);
        if (lane == 0) g_rownz[b * 32 + rt] = bits;
    }
}

// -------------------- K4a: sequential resolve (sparse, 1 warp/image) --------
// mask[i] only sets bits j>i, so only rows with nonzero mask rows can change
// state. Iterate those (few) rows in index order; lane owns removed word lane.
__global__ void k_resolve()
{
    int b    = blockIdx.x;
    int lane = threadIdx.x;   // 32 threads
    unsigned rem = 0;

    for (int rt = 0; rt < 32; rt++) {
        unsigned nz = g_rownz[b * 32 + rt];   // uniform across lanes
        while (nz) {
            int r = __ffs(nz) - 1;
            nz &= nz - 1;
            int i = rt * 32 + r;
            unsigned w  = __shfl_sync(0xffffffffu, rem, i >> 5);
            unsigned ib = (w >> (i & 31)) & 1u;
            int kept = 0;
            if (lane == 0) {
                float v = g_cand[((size_t)b * TOPK + i) * 8 + 6];
                kept = (!ib) && (v != 0.0f);
            }
            kept = __shfl_sync(0xffffffffu, kept, 0);
            if (kept)
                rem |= g_mask[(((size_t)b * TOPK) + i) * 32 + lane];
        }
    }
    g_removed[b * 32 + lane] = rem;
}

// -------------------- K4b: emit --------------------------------------------
__global__ void k_emit(float* __restrict__ out, int out_size)
{
    int b = blockIdx.y;
    int j = blockIdx.x * blockDim.x + threadIdx.x;   // 0..1023

    unsigned rem = g_removed[b * 32 + (j >> 5)];
    const float4* cr = reinterpret_cast<const float4*>(&g_cand[((size_t)b * TOPK + j) * 8]);
    float valid = cr[1].z;
    bool keep = (valid != 0.0f) && !((rem >> (j & 31)) & 1u);

    int m = g_topidx[b * TOPK + j];
    const float4* dr = reinterpret_cast<const float4*>(&g_det[((size_t)b * NBOX + m) * 8]);
    float4 d0 = dr[0], d1 = dr[1];
    float o[7] = {d0.x, d0.y, d0.z, d0.w, d1.x, d1.y, d1.z};

    size_t base = ((size_t)b * TOPK + j) * 7;
    #pragma unroll
    for (int k = 0; k < 7; k++)
        out[base + k] = keep ? __fmul_rn(8.0f, o[k]) : 0.0f;

    if (out_size >= BATCH * TOPK * 7 + BATCH * TOPK)
        out[(size_t)BATCH * TOPK * 7 + (size_t)b * TOPK + j] = keep ? 1.0f : 0.0f;
}

// -------------------- launch -----------------------------------------------
extern "C" void kernel_launch(void* const* d_in, const int* in_sizes, int n_in,
                              void* d_out, int out_size)
{
    const float* in = (const float*)d_in[0];
    float* out = (float*)d_out;

    k_decode<<<dim3(16, BATCH), 256>>>(in);
    k_select<<<BATCH, 1024>>>();
    k_mask<<<dim3(32, BATCH), 1024>>>();
    k_resolve<<<BATCH, 32>>>();
    k_emit<<<dim3(8, BATCH), 128>>>(out, out_size);
}